// round 4
// baseline (speedup 1.0000x reference)
#include <cuda_runtime.h>

// VDEncoderDecoder: stacked LSTM encoder (8->32->8->1, T=48) + decoder
// (1->2->2->1, 60 steps) + fused fc via g = fc2_w @ fc1_w.
// E=2 batch elements per thread: weight registers (loaded from smem once per
// warp per timestep) are reused for both elements, halving L1 wavefront
// traffic per element. Gates packed (i,f)/(g,o) in fma.rn.f32x2.

#define TPB 128
static constexpr int BATCH = 32768;
static constexpr int T = 48;
static constexpr int NTHREADS = BATCH / 2;

// packed (u64) smem offsets
static constexpr int P_E1IH = 0;     // (gp*32+u)*8+d        512
static constexpr int P_E1HH = 512;   // (gp*32+u)*32+j       2048
static constexpr int P_B1   = 2560;  // gp*32+u              64
static constexpr int P_E2IH = 2624;  // (gp*8+u)*32+d        512
static constexpr int P_E2HH = 3136;  // (gp*8+u)*8+j         128
static constexpr int P_B2   = 3264;  // gp*8+u               16
static constexpr int P_G    = 3280;  // t*6+j2               360
static constexpr int P_TOTAL = 3640;

// scalar (float) smem offsets
static constexpr int S_W3IH = 0;    // 32
static constexpr int S_W3HH = 32;   // 4
static constexpr int S_B3   = 36;   // 4
static constexpr int S_D1IH = 40;   // 8
static constexpr int S_D1HH = 48;   // 16
static constexpr int S_BD1  = 64;   // 8
static constexpr int S_D2IH = 72;   // 16
static constexpr int S_D2HH = 88;   // 16
static constexpr int S_BD2  = 104;  // 8
static constexpr int S_D3IH = 112;  // 8
static constexpr int S_D3HH = 120;  // 4
static constexpr int S_BD3  = 124;  // 4
static constexpr int S_CB   = 128;  // 12
static constexpr int S_TOTAL = 140;

typedef unsigned long long u64;

__device__ __forceinline__ u64 fma2(u64 a, u64 b, u64 c) {
    u64 d;
    asm("fma.rn.f32x2 %0, %1, %2, %3;" : "=l"(d) : "l"(a), "l"(b), "l"(c));
    return d;
}
__device__ __forceinline__ u64 pack2(float v) {
    u64 r;
    asm("mov.b64 %0, {%1, %1};" : "=l"(r) : "f"(v));
    return r;
}
__device__ __forceinline__ u64 pack2f(float lo, float hi) {
    u64 r;
    asm("mov.b64 %0, {%1, %2};" : "=l"(r) : "f"(lo), "f"(hi));
    return r;
}
__device__ __forceinline__ void unpack2(u64 v, float& lo, float& hi) {
    asm("mov.b64 {%0, %1}, %2;" : "=f"(lo), "=f"(hi) : "l"(v));
}

__device__ __forceinline__ float sigf(float x) {
    return __fdividef(1.0f, 1.0f + __expf(-x));
}
__device__ __forceinline__ float tanhx(float x) {
    float e = __expf(2.0f * x);
    return 1.0f - __fdividef(2.0f, e + 1.0f);
}

// Small scalar LSTM cell, fully unrolled (register-resident state).
template<int H, int DIN>
__device__ __forceinline__ void lstm_small(
    const float* __restrict__ wih, const float* __restrict__ whh,
    const float* __restrict__ bias,
    const float (&xin)[DIN], float (&h)[H], float (&c)[H])
{
    float hn[H];
#pragma unroll
    for (int u = 0; u < H; ++u) {
        float a0 = bias[u];
        float a1 = bias[H + u];
        float a2 = bias[2 * H + u];
        float a3 = bias[3 * H + u];
#pragma unroll
        for (int d = 0; d < DIN; ++d) {
            float xv = xin[d];
            a0 = fmaf(xv, wih[u * DIN + d], a0);
            a1 = fmaf(xv, wih[(H + u) * DIN + d], a1);
            a2 = fmaf(xv, wih[(2 * H + u) * DIN + d], a2);
            a3 = fmaf(xv, wih[(3 * H + u) * DIN + d], a3);
        }
#pragma unroll
        for (int j = 0; j < H; ++j) {
            float hv = h[j];
            a0 = fmaf(hv, whh[u * H + j], a0);
            a1 = fmaf(hv, whh[(H + u) * H + j], a1);
            a2 = fmaf(hv, whh[(2 * H + u) * H + j], a2);
            a3 = fmaf(hv, whh[(3 * H + u) * H + j], a3);
        }
        float ig = sigf(a0);
        float fg = sigf(a1);
        float gg = tanhx(a2);
        float og = sigf(a3);
        float cn = fmaf(fg, c[u], ig * gg);
        c[u] = cn;
        hn[u] = og * tanhx(cn);
    }
#pragma unroll
    for (int u = 0; u < H; ++u) h[u] = hn[u];
}

__global__ void __launch_bounds__(TPB)
vd_encdec_kernel(
    const float* __restrict__ x,
    const float* __restrict__ w1ih, const float* __restrict__ w1hh, const float* __restrict__ b1,
    const float* __restrict__ w2ih, const float* __restrict__ w2hh, const float* __restrict__ b2,
    const float* __restrict__ w3ih, const float* __restrict__ w3hh, const float* __restrict__ b3,
    const float* __restrict__ d1ih, const float* __restrict__ d1hh, const float* __restrict__ bd1,
    const float* __restrict__ d2ih, const float* __restrict__ d2hh, const float* __restrict__ bd2,
    const float* __restrict__ d3ih, const float* __restrict__ d3hh, const float* __restrict__ bd3,
    const float* __restrict__ fc1w, const float* __restrict__ fc1b,
    const float* __restrict__ fc2w, const float* __restrict__ fc2b,
    float* __restrict__ out)
{
    __shared__ __align__(16) u64 swp[P_TOTAL];
    __shared__ float sws[S_TOTAL];
    const int tid = threadIdx.x;

    // ---- stage packed weights ----
    for (int i = tid; i < 512; i += TPB) {
        int gp = i >> 8, rem = i & 255, u = rem >> 3, d = rem & 7;
        int r0 = gp * 64 + u, r1 = r0 + 32;
        swp[P_E1IH + i] = pack2f(w1ih[r0 * 8 + d], w1ih[r1 * 8 + d]);
    }
    for (int i = tid; i < 2048; i += TPB) {
        int gp = i >> 10, rem = i & 1023, u = rem >> 5, j = rem & 31;
        int r0 = gp * 64 + u, r1 = r0 + 32;
        swp[P_E1HH + i] = pack2f(w1hh[r0 * 32 + j], w1hh[r1 * 32 + j]);
    }
    for (int i = tid; i < 64; i += TPB) {
        int gp = i >> 5, u = i & 31;
        swp[P_B1 + i] = pack2f(b1[gp * 64 + u], b1[gp * 64 + 32 + u]);
    }
    for (int i = tid; i < 512; i += TPB) {
        int gp = i >> 8, rem = i & 255, u = rem >> 5, d = rem & 31;
        int r0 = gp * 16 + u, r1 = r0 + 8;
        swp[P_E2IH + i] = pack2f(w2ih[r0 * 32 + d], w2ih[r1 * 32 + d]);
    }
    for (int i = tid; i < 128; i += TPB) {
        int gp = i >> 6, rem = i & 63, u = rem >> 3, j = rem & 7;
        int r0 = gp * 16 + u, r1 = r0 + 8;
        swp[P_E2HH + i] = pack2f(w2hh[r0 * 8 + j], w2hh[r1 * 8 + j]);
    }
    for (int i = tid; i < 16; i += TPB) {
        int gp = i >> 3, u = i & 7;
        swp[P_B2 + i] = pack2f(b2[gp * 16 + u], b2[gp * 16 + 8 + u]);
    }
    for (int i = tid; i < 360; i += TPB) {
        int t = i / 6, j2 = i % 6;
        float g0 = 0.0f, g1 = 0.0f;
        for (int k = 0; k < 32; ++k) {
            float f1 = fc1w[k * 60 + t];
            g0 = fmaf(fc2w[(2 * j2) * 32 + k], f1, g0);
            g1 = fmaf(fc2w[(2 * j2 + 1) * 32 + k], f1, g1);
        }
        swp[P_G + i] = pack2f(g0, g1);
    }
    for (int i = tid; i < 32; i += TPB) sws[S_W3IH + i] = w3ih[i];
    if (tid < 4)  sws[S_W3HH + tid] = w3hh[tid];
    if (tid < 4)  sws[S_B3 + tid] = b3[tid];
    if (tid < 8)  sws[S_D1IH + tid] = d1ih[tid];
    if (tid < 16) sws[S_D1HH + tid] = d1hh[tid];
    if (tid < 8)  sws[S_BD1 + tid] = bd1[tid];
    if (tid < 16) sws[S_D2IH + tid] = d2ih[tid];
    if (tid < 16) sws[S_D2HH + tid] = d2hh[tid];
    if (tid < 8)  sws[S_BD2 + tid] = bd2[tid];
    if (tid < 8)  sws[S_D3IH + tid] = d3ih[tid];
    if (tid < 4)  sws[S_D3HH + tid] = d3hh[tid];
    if (tid < 4)  sws[S_BD3 + tid] = bd3[tid];
    if (tid < 12) {
        float a = fc2b[tid];
        for (int k = 0; k < 32; ++k)
            a = fmaf(fc2w[tid * 32 + k], fc1b[k], a);
        sws[S_CB + tid] = a;
    }
    __syncthreads();

    const int pair = blockIdx.x * TPB + tid;   // 0..16383
    const float* xb0 = x + (size_t)(2 * pair) * (T * 8);
    const float* xb1 = xb0 + T * 8;

    // splatted old-h (registers; statically indexed only)
    u64 hp1a[32], hp1b[32], hp2a[8], hp2b[8];
    // runtime-indexed state (local, coalesced per lane)
    float c1a[32], c1b[32], hn1a[32], hn1b[32];
    float c2a[8], c2b[8], hn2a[8], hn2b[8];
    float h3a[1], c3a[1], h3b[1], c3b[1];
    float hd1a[2], cd1a[2], hd2a[2], cd2a[2], hd3a[1], cd3a[1];
    float hd1b[2], cd1b[2], hd2b[2], cd2b[2], hd3b[1], cd3b[1];
    u64 acc6a[6], acc6b[6];

#pragma unroll
    for (int i = 0; i < 32; ++i) { hp1a[i] = 0ULL; hp1b[i] = 0ULL; c1a[i] = 0.0f; c1b[i] = 0.0f; }
#pragma unroll
    for (int i = 0; i < 8; ++i) { hp2a[i] = 0ULL; hp2b[i] = 0ULL; c2a[i] = 0.0f; c2b[i] = 0.0f; hn2a[i] = 0.0f; hn2b[i] = 0.0f; }
    h3a[0] = 0.0f; c3a[0] = 0.0f; h3b[0] = 0.0f; c3b[0] = 0.0f;
#pragma unroll
    for (int i = 0; i < 2; ++i) {
        hd1a[i] = 0.0f; cd1a[i] = 0.0f; hd2a[i] = 0.0f; cd2a[i] = 0.0f;
        hd1b[i] = 0.0f; cd1b[i] = 0.0f; hd2b[i] = 0.0f; cd2b[i] = 0.0f;
    }
    hd3a[0] = 0.0f; cd3a[0] = 0.0f; hd3b[0] = 0.0f; cd3b[0] = 0.0f;
#pragma unroll
    for (int i = 0; i < 6; ++i) { acc6a[i] = 0ULL; acc6b[i] = 0ULL; }

    // ---- fused steps t = 0..47 ----
#pragma unroll 1
    for (int t = 0; t < T; ++t) {
        float4 xa0 = *reinterpret_cast<const float4*>(xb0 + t * 8);
        float4 xc0 = *reinterpret_cast<const float4*>(xb0 + t * 8 + 4);
        float4 xa1 = *reinterpret_cast<const float4*>(xb1 + t * 8);
        float4 xc1 = *reinterpret_cast<const float4*>(xb1 + t * 8 + 4);
        u64 xpa[8], xpb[8];
        xpa[0] = pack2(xa0.x); xpa[1] = pack2(xa0.y); xpa[2] = pack2(xa0.z); xpa[3] = pack2(xa0.w);
        xpa[4] = pack2(xc0.x); xpa[5] = pack2(xc0.y); xpa[6] = pack2(xc0.z); xpa[7] = pack2(xc0.w);
        xpb[0] = pack2(xa1.x); xpb[1] = pack2(xa1.y); xpb[2] = pack2(xa1.z); xpb[3] = pack2(xa1.w);
        xpb[4] = pack2(xc1.x); xpb[5] = pack2(xc1.y); xpb[6] = pack2(xc1.z); xpb[7] = pack2(xc1.w);

        // ---- e1: H=32, DIN=8; weights loaded once, used for both elements ----
#pragma unroll 1
        for (int u = 0; u < 32; ++u) {
            u64 bif = swp[P_B1 + u];
            u64 bgo = swp[P_B1 + 32 + u];
            u64 aif0 = bif, ago0 = bgo, aif1 = bif, ago1 = bgo;
            const ulonglong2* wif = reinterpret_cast<const ulonglong2*>(swp + P_E1IH + u * 8);
            const ulonglong2* wgo = reinterpret_cast<const ulonglong2*>(swp + P_E1IH + (32 + u) * 8);
#pragma unroll
            for (int dd = 0; dd < 4; ++dd) {
                ulonglong2 qa = wif[dd];
                ulonglong2 qb = wgo[dd];
                aif0 = fma2(qa.x, xpa[2 * dd], aif0);
                aif1 = fma2(qa.x, xpb[2 * dd], aif1);
                ago0 = fma2(qb.x, xpa[2 * dd], ago0);
                ago1 = fma2(qb.x, xpb[2 * dd], ago1);
                aif0 = fma2(qa.y, xpa[2 * dd + 1], aif0);
                aif1 = fma2(qa.y, xpb[2 * dd + 1], aif1);
                ago0 = fma2(qb.y, xpa[2 * dd + 1], ago0);
                ago1 = fma2(qb.y, xpb[2 * dd + 1], ago1);
            }
            const ulonglong2* vif = reinterpret_cast<const ulonglong2*>(swp + P_E1HH + u * 32);
            const ulonglong2* vgo = reinterpret_cast<const ulonglong2*>(swp + P_E1HH + (32 + u) * 32);
#pragma unroll
            for (int jj = 0; jj < 16; ++jj) {
                ulonglong2 qa = vif[jj];
                ulonglong2 qb = vgo[jj];
                aif0 = fma2(qa.x, hp1a[2 * jj], aif0);
                aif1 = fma2(qa.x, hp1b[2 * jj], aif1);
                ago0 = fma2(qb.x, hp1a[2 * jj], ago0);
                ago1 = fma2(qb.x, hp1b[2 * jj], ago1);
                aif0 = fma2(qa.y, hp1a[2 * jj + 1], aif0);
                aif1 = fma2(qa.y, hp1b[2 * jj + 1], aif1);
                ago0 = fma2(qb.y, hp1a[2 * jj + 1], ago0);
                ago1 = fma2(qb.y, hp1b[2 * jj + 1], ago1);
            }
            {
                float ai, af, ag, ao;
                unpack2(aif0, ai, af);
                unpack2(ago0, ag, ao);
                float ig = sigf(ai), fg = sigf(af), gg = tanhx(ag), og = sigf(ao);
                float cn = fmaf(fg, c1a[u], ig * gg);
                c1a[u] = cn;
                hn1a[u] = og * tanhx(cn);
            }
            {
                float ai, af, ag, ao;
                unpack2(aif1, ai, af);
                unpack2(ago1, ag, ao);
                float ig = sigf(ai), fg = sigf(af), gg = tanhx(ag), og = sigf(ao);
                float cn = fmaf(fg, c1b[u], ig * gg);
                c1b[u] = cn;
                hn1b[u] = og * tanhx(cn);
            }
        }
#pragma unroll
        for (int j = 0; j < 32; ++j) { hp1a[j] = pack2(hn1a[j]); hp1b[j] = pack2(hn1b[j]); }

        // ---- e2: H=8, DIN=32 ----
#pragma unroll 1
        for (int u = 0; u < 8; ++u) {
            u64 bif = swp[P_B2 + u];
            u64 bgo = swp[P_B2 + 8 + u];
            u64 aif0 = bif, ago0 = bgo, aif1 = bif, ago1 = bgo;
            const ulonglong2* wif = reinterpret_cast<const ulonglong2*>(swp + P_E2IH + u * 32);
            const ulonglong2* wgo = reinterpret_cast<const ulonglong2*>(swp + P_E2IH + (8 + u) * 32);
#pragma unroll
            for (int dd = 0; dd < 16; ++dd) {
                ulonglong2 qa = wif[dd];
                ulonglong2 qb = wgo[dd];
                aif0 = fma2(qa.x, hp1a[2 * dd], aif0);
                aif1 = fma2(qa.x, hp1b[2 * dd], aif1);
                ago0 = fma2(qb.x, hp1a[2 * dd], ago0);
                ago1 = fma2(qb.x, hp1b[2 * dd], ago1);
                aif0 = fma2(qa.y, hp1a[2 * dd + 1], aif0);
                aif1 = fma2(qa.y, hp1b[2 * dd + 1], aif1);
                ago0 = fma2(qb.y, hp1a[2 * dd + 1], ago0);
                ago1 = fma2(qb.y, hp1b[2 * dd + 1], ago1);
            }
            const ulonglong2* vif = reinterpret_cast<const ulonglong2*>(swp + P_E2HH + u * 8);
            const ulonglong2* vgo = reinterpret_cast<const ulonglong2*>(swp + P_E2HH + (8 + u) * 8);
#pragma unroll
            for (int jj = 0; jj < 4; ++jj) {
                ulonglong2 qa = vif[jj];
                ulonglong2 qb = vgo[jj];
                aif0 = fma2(qa.x, hp2a[2 * jj], aif0);
                aif1 = fma2(qa.x, hp2b[2 * jj], aif1);
                ago0 = fma2(qb.x, hp2a[2 * jj], ago0);
                ago1 = fma2(qb.x, hp2b[2 * jj], ago1);
                aif0 = fma2(qa.y, hp2a[2 * jj + 1], aif0);
                aif1 = fma2(qa.y, hp2b[2 * jj + 1], aif1);
                ago0 = fma2(qb.y, hp2a[2 * jj + 1], ago0);
                ago1 = fma2(qb.y, hp2b[2 * jj + 1], ago1);
            }
            {
                float ai, af, ag, ao;
                unpack2(aif0, ai, af);
                unpack2(ago0, ag, ao);
                float ig = sigf(ai), fg = sigf(af), gg = tanhx(ag), og = sigf(ao);
                float cn = fmaf(fg, c2a[u], ig * gg);
                c2a[u] = cn;
                hn2a[u] = og * tanhx(cn);
            }
            {
                float ai, af, ag, ao;
                unpack2(aif1, ai, af);
                unpack2(ago1, ag, ao);
                float ig = sigf(ai), fg = sigf(af), gg = tanhx(ag), og = sigf(ao);
                float cn = fmaf(fg, c2b[u], ig * gg);
                c2b[u] = cn;
                hn2b[u] = og * tanhx(cn);
            }
        }
#pragma unroll
        for (int j = 0; j < 8; ++j) { hp2a[j] = pack2(hn2a[j]); hp2b[j] = pack2(hn2b[j]); }

        // ---- e3 + decoder (scalar, tiny) for both elements ----
        lstm_small<1, 8>(sws + S_W3IH, sws + S_W3HH, sws + S_B3, hn2a, h3a, c3a);
        lstm_small<1, 8>(sws + S_W3IH, sws + S_W3HH, sws + S_B3, hn2b, h3b, c3b);

        float dva[1] = { h3a[0] };
        float dvb[1] = { h3b[0] };
        lstm_small<2, 1>(sws + S_D1IH, sws + S_D1HH, sws + S_BD1, dva, hd1a, cd1a);
        lstm_small<2, 1>(sws + S_D1IH, sws + S_D1HH, sws + S_BD1, dvb, hd1b, cd1b);
        lstm_small<2, 2>(sws + S_D2IH, sws + S_D2HH, sws + S_BD2, hd1a, hd2a, cd2a);
        lstm_small<2, 2>(sws + S_D2IH, sws + S_D2HH, sws + S_BD2, hd1b, hd2b, cd2b);
        lstm_small<1, 2>(sws + S_D3IH, sws + S_D3HH, sws + S_BD3, hd2a, hd3a, cd3a);
        lstm_small<1, 2>(sws + S_D3IH, sws + S_D3HH, sws + S_BD3, hd2b, hd3b, cd3b);

        u64 ypa = pack2(hd3a[0]);
        u64 ypb = pack2(hd3b[0]);
        const u64* gr = swp + P_G + t * 6;
#pragma unroll
        for (int j = 0; j < 6; ++j) {
            u64 g = gr[j];
            acc6a[j] = fma2(ypa, g, acc6a[j]);
            acc6b[j] = fma2(ypb, g, acc6b[j]);
        }
    }

    // ---- aux steps t = 48..59: decoder input = x[b, t-12, 4] ----
#pragma unroll 1
    for (int t = T; t < 60; ++t) {
        float dva[1] = { xb0[(t - 12) * 8 + 4] };
        float dvb[1] = { xb1[(t - 12) * 8 + 4] };
        lstm_small<2, 1>(sws + S_D1IH, sws + S_D1HH, sws + S_BD1, dva, hd1a, cd1a);
        lstm_small<2, 1>(sws + S_D1IH, sws + S_D1HH, sws + S_BD1, dvb, hd1b, cd1b);
        lstm_small<2, 2>(sws + S_D2IH, sws + S_D2HH, sws + S_BD2, hd1a, hd2a, cd2a);
        lstm_small<2, 2>(sws + S_D2IH, sws + S_D2HH, sws + S_BD2, hd1b, hd2b, cd2b);
        lstm_small<1, 2>(sws + S_D3IH, sws + S_D3HH, sws + S_BD3, hd2a, hd3a, cd3a);
        lstm_small<1, 2>(sws + S_D3IH, sws + S_D3HH, sws + S_BD3, hd2b, hd3b, cd3b);

        u64 ypa = pack2(hd3a[0]);
        u64 ypb = pack2(hd3b[0]);
        const u64* gr = swp + P_G + t * 6;
#pragma unroll
        for (int j = 0; j < 6; ++j) {
            u64 g = gr[j];
            acc6a[j] = fma2(ypa, g, acc6a[j]);
            acc6b[j] = fma2(ypb, g, acc6b[j]);
        }
    }

    // ---- epilogue ----
    float ra[12], rb[12];
#pragma unroll
    for (int j = 0; j < 6; ++j) {
        float lo, hi;
        unpack2(acc6a[j], lo, hi);
        ra[2 * j] = lo + sws[S_CB + 2 * j];
        ra[2 * j + 1] = hi + sws[S_CB + 2 * j + 1];
        unpack2(acc6b[j], lo, hi);
        rb[2 * j] = lo + sws[S_CB + 2 * j];
        rb[2 * j + 1] = hi + sws[S_CB + 2 * j + 1];
    }
    float4* op0 = reinterpret_cast<float4*>(out + (size_t)(2 * pair) * 12);
    op0[0] = make_float4(ra[0], ra[1], ra[2], ra[3]);
    op0[1] = make_float4(ra[4], ra[5], ra[6], ra[7]);
    op0[2] = make_float4(ra[8], ra[9], ra[10], ra[11]);
    float4* op1 = reinterpret_cast<float4*>(out + (size_t)(2 * pair + 1) * 12);
    op1[0] = make_float4(rb[0], rb[1], rb[2], rb[3]);
    op1[1] = make_float4(rb[4], rb[5], rb[6], rb[7]);
    op1[2] = make_float4(rb[8], rb[9], rb[10], rb[11]);
}

extern "C" void kernel_launch(void* const* d_in, const int* in_sizes, int n_in,
                              void* d_out, int out_size) {
    (void)in_sizes; (void)n_in; (void)out_size;
    const float* x    = (const float*)d_in[0];
    const float* w1ih = (const float*)d_in[1];
    const float* w1hh = (const float*)d_in[2];
    const float* b1   = (const float*)d_in[3];
    const float* w2ih = (const float*)d_in[4];
    const float* w2hh = (const float*)d_in[5];
    const float* b2   = (const float*)d_in[6];
    const float* w3ih = (const float*)d_in[7];
    const float* w3hh = (const float*)d_in[8];
    const float* b3   = (const float*)d_in[9];
    const float* d1ih = (const float*)d_in[10];
    const float* d1hh = (const float*)d_in[11];
    const float* bd1  = (const float*)d_in[12];
    const float* d2ih = (const float*)d_in[13];
    const float* d2hh = (const float*)d_in[14];
    const float* bd2  = (const float*)d_in[15];
    const float* d3ih = (const float*)d_in[16];
    const float* d3hh = (const float*)d_in[17];
    const float* bd3  = (const float*)d_in[18];
    const float* fc1w = (const float*)d_in[19];
    const float* fc1b = (const float*)d_in[20];
    const float* fc2w = (const float*)d_in[21];
    const float* fc2b = (const float*)d_in[22];
    float* out = (float*)d_out;

    dim3 grid(NTHREADS / TPB);
    dim3 block(TPB);
    vd_encdec_kernel<<<grid, block>>>(
        x, w1ih, w1hh, b1, w2ih, w2hh, b2, w3ih, w3hh, b3,
        d1ih, d1hh, bd1, d2ih, d2hh, bd2, d3ih, d3hh, bd3,
        fc1w, fc1b, fc2w, fc2b, out);
}

// round 5
// speedup vs baseline: 2.0367x; 2.0367x over previous
#include <cuda_runtime.h>

// VDEncoderDecoder: stacked LSTM encoder (8->32->8->1, T=48) + decoder
// (1->2->2->1, 60 steps) + fused fc via g = fc2_w @ fc1_w.
// E=2 batch elements per thread with fma.rn.f32x2 packed over the ELEMENT
// pair (not gates): h state is pair-packed (no register doubling), weights
// are loaded once per warp per timestep (LDS.128) and splat on the fly.

#define TPB 128
static constexpr int BATCH = 32768;
static constexpr int T = 48;
static constexpr int NTHREADS = BATCH / 2;

typedef unsigned long long u64;

// float smem offsets (plain row-major weight layouts)
static constexpr int F_W1IH = 0;       // [128 x 8]
static constexpr int F_W1HH = 1024;    // [128 x 32]
static constexpr int F_W2IH = 5120;    // [32 x 32]
static constexpr int F_W2HH = 6144;    // [32 x 8]
static constexpr int F_SMALL = 6400;   // small scalar block below
// small block offsets (relative to F_SMALL)
static constexpr int S_W3IH = 0;    // 32
static constexpr int S_W3HH = 32;   // 4
static constexpr int S_B3   = 36;   // 4
static constexpr int S_D1IH = 40;   // 8
static constexpr int S_D1HH = 48;   // 16
static constexpr int S_BD1  = 64;   // 8
static constexpr int S_D2IH = 72;   // 16
static constexpr int S_D2HH = 88;   // 16
static constexpr int S_BD2  = 104;  // 8
static constexpr int S_D3IH = 112;  // 8
static constexpr int S_D3HH = 120;  // 4
static constexpr int S_BD3  = 124;  // 4
static constexpr int S_CB   = 128;  // 12
static constexpr int F_TOTAL = 6400 + 140;

// u64 smem offsets (splat bias pairs + fused fc pairs)
static constexpr int P_B1 = 0;     // 128 (splat)
static constexpr int P_B2 = 128;   // 32  (splat)
static constexpr int P_G  = 160;   // 360 (t*6 + j2, packed over output dims)
static constexpr int P_TOTAL = 520;

__device__ __forceinline__ u64 fma2(u64 a, u64 b, u64 c) {
    u64 d;
    asm("fma.rn.f32x2 %0, %1, %2, %3;" : "=l"(d) : "l"(a), "l"(b), "l"(c));
    return d;
}
__device__ __forceinline__ u64 pack2(float v) {
    u64 r;
    asm("mov.b64 %0, {%1, %1};" : "=l"(r) : "f"(v));
    return r;
}
__device__ __forceinline__ u64 pack2f(float lo, float hi) {
    u64 r;
    asm("mov.b64 %0, {%1, %2};" : "=l"(r) : "f"(lo), "f"(hi));
    return r;
}
__device__ __forceinline__ void unpack2(u64 v, float& lo, float& hi) {
    asm("mov.b64 {%0, %1}, %2;" : "=f"(lo), "=f"(hi) : "l"(v));
}

__device__ __forceinline__ float sigf(float x) {
    return __fdividef(1.0f, 1.0f + __expf(-x));
}
__device__ __forceinline__ float tanhx(float x) {
    float e = __expf(2.0f * x);
    return 1.0f - __fdividef(2.0f, e + 1.0f);
}

// Small scalar LSTM cell, fully unrolled.
template<int H, int DIN>
__device__ __forceinline__ void lstm_small(
    const float* __restrict__ wih, const float* __restrict__ whh,
    const float* __restrict__ bias,
    const float (&xin)[DIN], float (&h)[H], float (&c)[H])
{
    float hn[H];
#pragma unroll
    for (int u = 0; u < H; ++u) {
        float a0 = bias[u];
        float a1 = bias[H + u];
        float a2 = bias[2 * H + u];
        float a3 = bias[3 * H + u];
#pragma unroll
        for (int d = 0; d < DIN; ++d) {
            float xv = xin[d];
            a0 = fmaf(xv, wih[u * DIN + d], a0);
            a1 = fmaf(xv, wih[(H + u) * DIN + d], a1);
            a2 = fmaf(xv, wih[(2 * H + u) * DIN + d], a2);
            a3 = fmaf(xv, wih[(3 * H + u) * DIN + d], a3);
        }
#pragma unroll
        for (int j = 0; j < H; ++j) {
            float hv = h[j];
            a0 = fmaf(hv, whh[u * H + j], a0);
            a1 = fmaf(hv, whh[(H + u) * H + j], a1);
            a2 = fmaf(hv, whh[(2 * H + u) * H + j], a2);
            a3 = fmaf(hv, whh[(3 * H + u) * H + j], a3);
        }
        float ig = sigf(a0);
        float fg = sigf(a1);
        float gg = tanhx(a2);
        float og = sigf(a3);
        float cn = fmaf(fg, c[u], ig * gg);
        c[u] = cn;
        hn[u] = og * tanhx(cn);
    }
#pragma unroll
    for (int u = 0; u < H; ++u) h[u] = hn[u];
}

__global__ void __launch_bounds__(TPB, 1)
vd_encdec_kernel(
    const float* __restrict__ x,
    const float* __restrict__ w1ih, const float* __restrict__ w1hh, const float* __restrict__ b1,
    const float* __restrict__ w2ih, const float* __restrict__ w2hh, const float* __restrict__ b2,
    const float* __restrict__ w3ih, const float* __restrict__ w3hh, const float* __restrict__ b3,
    const float* __restrict__ d1ih, const float* __restrict__ d1hh, const float* __restrict__ bd1,
    const float* __restrict__ d2ih, const float* __restrict__ d2hh, const float* __restrict__ bd2,
    const float* __restrict__ d3ih, const float* __restrict__ d3hh, const float* __restrict__ bd3,
    const float* __restrict__ fc1w, const float* __restrict__ fc1b,
    const float* __restrict__ fc2w, const float* __restrict__ fc2b,
    float* __restrict__ out)
{
    __shared__ __align__(16) float swf[F_TOTAL];
    __shared__ __align__(16) u64 swp[P_TOTAL];
    const int tid = threadIdx.x;

    // ---- stage weights (plain layouts) ----
    for (int i = tid; i < 1024; i += TPB) swf[F_W1IH + i] = w1ih[i];
    for (int i = tid; i < 4096; i += TPB) swf[F_W1HH + i] = w1hh[i];
    for (int i = tid; i < 1024; i += TPB) swf[F_W2IH + i] = w2ih[i];
    for (int i = tid; i < 256;  i += TPB) swf[F_W2HH + i] = w2hh[i];
    for (int i = tid; i < 128;  i += TPB) swp[P_B1 + i] = pack2(b1[i]);
    for (int i = tid; i < 32;   i += TPB) swp[P_B2 + i] = pack2(b2[i]);
    // fused fc: g[t][j] = sum_k fc2w[j,k]*fc1w[k,t]; packed over output-dim pairs
    for (int i = tid; i < 360; i += TPB) {
        int t = i / 6, j2 = i % 6;
        float g0 = 0.0f, g1 = 0.0f;
        for (int k = 0; k < 32; ++k) {
            float f1 = fc1w[k * 60 + t];
            g0 = fmaf(fc2w[(2 * j2) * 32 + k], f1, g0);
            g1 = fmaf(fc2w[(2 * j2 + 1) * 32 + k], f1, g1);
        }
        swp[P_G + i] = pack2f(g0, g1);
    }
    float* sws = swf + F_SMALL;
    for (int i = tid; i < 32; i += TPB) sws[S_W3IH + i] = w3ih[i];
    if (tid < 4)  sws[S_W3HH + tid] = w3hh[tid];
    if (tid < 4)  sws[S_B3 + tid] = b3[tid];
    if (tid < 8)  sws[S_D1IH + tid] = d1ih[tid];
    if (tid < 16) sws[S_D1HH + tid] = d1hh[tid];
    if (tid < 8)  sws[S_BD1 + tid] = bd1[tid];
    if (tid < 16) sws[S_D2IH + tid] = d2ih[tid];
    if (tid < 16) sws[S_D2HH + tid] = d2hh[tid];
    if (tid < 8)  sws[S_BD2 + tid] = bd2[tid];
    if (tid < 8)  sws[S_D3IH + tid] = d3ih[tid];
    if (tid < 4)  sws[S_D3HH + tid] = d3hh[tid];
    if (tid < 4)  sws[S_BD3 + tid] = bd3[tid];
    if (tid < 12) {
        float a = fc2b[tid];
        for (int k = 0; k < 32; ++k)
            a = fmaf(fc2w[tid * 32 + k], fc1b[k], a);
        sws[S_CB + tid] = a;
    }
    __syncthreads();

    const int pair = blockIdx.x * TPB + tid;   // 0..16383
    const float* xb0 = x + (size_t)(2 * pair) * (T * 8);
    const float* xb1 = xb0 + T * 8;

    // element-pair-packed state
    u64 hp1[32];            // registers (statically indexed)
    u64 hp2[8];
    u64 c1p[32];            // runtime-indexed (local ok)
    u64 c2p[8];
    u64 hn1p[32], hn2p[8];  // runtime-indexed scratch
    float hn2a[8], hn2b[8]; // scalar h2 for e3 input
    float h3a[1], c3a[1], h3b[1], c3b[1];
    float hd1a[2], cd1a[2], hd2a[2], cd2a[2], hd3a[1], cd3a[1];
    float hd1b[2], cd1b[2], hd2b[2], cd2b[2], hd3b[1], cd3b[1];
    u64 acc6a[6], acc6b[6];

#pragma unroll
    for (int i = 0; i < 32; ++i) { hp1[i] = 0ULL; c1p[i] = 0ULL; }
#pragma unroll
    for (int i = 0; i < 8; ++i) { hp2[i] = 0ULL; c2p[i] = 0ULL; hn2a[i] = 0.0f; hn2b[i] = 0.0f; }
    h3a[0] = 0.0f; c3a[0] = 0.0f; h3b[0] = 0.0f; c3b[0] = 0.0f;
#pragma unroll
    for (int i = 0; i < 2; ++i) {
        hd1a[i] = 0.0f; cd1a[i] = 0.0f; hd2a[i] = 0.0f; cd2a[i] = 0.0f;
        hd1b[i] = 0.0f; cd1b[i] = 0.0f; hd2b[i] = 0.0f; cd2b[i] = 0.0f;
    }
    hd3a[0] = 0.0f; cd3a[0] = 0.0f; hd3b[0] = 0.0f; cd3b[0] = 0.0f;
#pragma unroll
    for (int i = 0; i < 6; ++i) { acc6a[i] = 0ULL; acc6b[i] = 0ULL; }

    // ---- fused steps t = 0..47 ----
#pragma unroll 1
    for (int t = 0; t < T; ++t) {
        float4 xa0 = *reinterpret_cast<const float4*>(xb0 + t * 8);
        float4 xc0 = *reinterpret_cast<const float4*>(xb0 + t * 8 + 4);
        float4 xa1 = *reinterpret_cast<const float4*>(xb1 + t * 8);
        float4 xc1 = *reinterpret_cast<const float4*>(xb1 + t * 8 + 4);
        u64 xp[8];
        xp[0] = pack2f(xa0.x, xa1.x); xp[1] = pack2f(xa0.y, xa1.y);
        xp[2] = pack2f(xa0.z, xa1.z); xp[3] = pack2f(xa0.w, xa1.w);
        xp[4] = pack2f(xc0.x, xc1.x); xp[5] = pack2f(xc0.y, xc1.y);
        xp[6] = pack2f(xc0.z, xc1.z); xp[7] = pack2f(xc0.w, xc1.w);

        // ---- e1: H=32, DIN=8; weights splat on the fly ----
#pragma unroll 1
        for (int u = 0; u < 32; ++u) {
            u64 a0 = swp[P_B1 + u];
            u64 a1 = swp[P_B1 + 32 + u];
            u64 a2 = swp[P_B1 + 64 + u];
            u64 a3 = swp[P_B1 + 96 + u];
            const float4* r0 = reinterpret_cast<const float4*>(swf + F_W1IH + u * 8);
            const float4* r1 = reinterpret_cast<const float4*>(swf + F_W1IH + (32 + u) * 8);
            const float4* r2 = reinterpret_cast<const float4*>(swf + F_W1IH + (64 + u) * 8);
            const float4* r3 = reinterpret_cast<const float4*>(swf + F_W1IH + (96 + u) * 8);
#pragma unroll
            for (int dd = 0; dd < 2; ++dd) {
                float4 q0 = r0[dd], q1 = r1[dd], q2 = r2[dd], q3 = r3[dd];
                a0 = fma2(pack2(q0.x), xp[4 * dd + 0], a0);
                a1 = fma2(pack2(q1.x), xp[4 * dd + 0], a1);
                a2 = fma2(pack2(q2.x), xp[4 * dd + 0], a2);
                a3 = fma2(pack2(q3.x), xp[4 * dd + 0], a3);
                a0 = fma2(pack2(q0.y), xp[4 * dd + 1], a0);
                a1 = fma2(pack2(q1.y), xp[4 * dd + 1], a1);
                a2 = fma2(pack2(q2.y), xp[4 * dd + 1], a2);
                a3 = fma2(pack2(q3.y), xp[4 * dd + 1], a3);
                a0 = fma2(pack2(q0.z), xp[4 * dd + 2], a0);
                a1 = fma2(pack2(q1.z), xp[4 * dd + 2], a1);
                a2 = fma2(pack2(q2.z), xp[4 * dd + 2], a2);
                a3 = fma2(pack2(q3.z), xp[4 * dd + 2], a3);
                a0 = fma2(pack2(q0.w), xp[4 * dd + 3], a0);
                a1 = fma2(pack2(q1.w), xp[4 * dd + 3], a1);
                a2 = fma2(pack2(q2.w), xp[4 * dd + 3], a2);
                a3 = fma2(pack2(q3.w), xp[4 * dd + 3], a3);
            }
            const float4* v0 = reinterpret_cast<const float4*>(swf + F_W1HH + u * 32);
            const float4* v1 = reinterpret_cast<const float4*>(swf + F_W1HH + (32 + u) * 32);
            const float4* v2 = reinterpret_cast<const float4*>(swf + F_W1HH + (64 + u) * 32);
            const float4* v3 = reinterpret_cast<const float4*>(swf + F_W1HH + (96 + u) * 32);
#pragma unroll
            for (int jj = 0; jj < 8; ++jj) {
                float4 q0 = v0[jj], q1 = v1[jj], q2 = v2[jj], q3 = v3[jj];
                a0 = fma2(pack2(q0.x), hp1[4 * jj + 0], a0);
                a1 = fma2(pack2(q1.x), hp1[4 * jj + 0], a1);
                a2 = fma2(pack2(q2.x), hp1[4 * jj + 0], a2);
                a3 = fma2(pack2(q3.x), hp1[4 * jj + 0], a3);
                a0 = fma2(pack2(q0.y), hp1[4 * jj + 1], a0);
                a1 = fma2(pack2(q1.y), hp1[4 * jj + 1], a1);
                a2 = fma2(pack2(q2.y), hp1[4 * jj + 1], a2);
                a3 = fma2(pack2(q3.y), hp1[4 * jj + 1], a3);
                a0 = fma2(pack2(q0.z), hp1[4 * jj + 2], a0);
                a1 = fma2(pack2(q1.z), hp1[4 * jj + 2], a1);
                a2 = fma2(pack2(q2.z), hp1[4 * jj + 2], a2);
                a3 = fma2(pack2(q3.z), hp1[4 * jj + 2], a3);
                a0 = fma2(pack2(q0.w), hp1[4 * jj + 3], a0);
                a1 = fma2(pack2(q1.w), hp1[4 * jj + 3], a1);
                a2 = fma2(pack2(q2.w), hp1[4 * jj + 3], a2);
                a3 = fma2(pack2(q3.w), hp1[4 * jj + 3], a3);
            }
            float iA, iB, fA, fB, gA, gB, oA, oB;
            unpack2(a0, iA, iB);
            unpack2(a1, fA, fB);
            unpack2(a2, gA, gB);
            unpack2(a3, oA, oB);
            float cA0, cB0;
            unpack2(c1p[u], cA0, cB0);
            float cA = fmaf(sigf(fA), cA0, sigf(iA) * tanhx(gA));
            float cB = fmaf(sigf(fB), cB0, sigf(iB) * tanhx(gB));
            c1p[u] = pack2f(cA, cB);
            float hA = sigf(oA) * tanhx(cA);
            float hB = sigf(oB) * tanhx(cB);
            hn1p[u] = pack2f(hA, hB);
        }
#pragma unroll
        for (int j = 0; j < 32; ++j) hp1[j] = hn1p[j];

        // ---- e2: H=8, DIN=32 ----
#pragma unroll 1
        for (int u = 0; u < 8; ++u) {
            u64 a0 = swp[P_B2 + u];
            u64 a1 = swp[P_B2 + 8 + u];
            u64 a2 = swp[P_B2 + 16 + u];
            u64 a3 = swp[P_B2 + 24 + u];
            const float4* r0 = reinterpret_cast<const float4*>(swf + F_W2IH + u * 32);
            const float4* r1 = reinterpret_cast<const float4*>(swf + F_W2IH + (8 + u) * 32);
            const float4* r2 = reinterpret_cast<const float4*>(swf + F_W2IH + (16 + u) * 32);
            const float4* r3 = reinterpret_cast<const float4*>(swf + F_W2IH + (24 + u) * 32);
#pragma unroll
            for (int dd = 0; dd < 8; ++dd) {
                float4 q0 = r0[dd], q1 = r1[dd], q2 = r2[dd], q3 = r3[dd];
                a0 = fma2(pack2(q0.x), hp1[4 * dd + 0], a0);
                a1 = fma2(pack2(q1.x), hp1[4 * dd + 0], a1);
                a2 = fma2(pack2(q2.x), hp1[4 * dd + 0], a2);
                a3 = fma2(pack2(q3.x), hp1[4 * dd + 0], a3);
                a0 = fma2(pack2(q0.y), hp1[4 * dd + 1], a0);
                a1 = fma2(pack2(q1.y), hp1[4 * dd + 1], a1);
                a2 = fma2(pack2(q2.y), hp1[4 * dd + 1], a2);
                a3 = fma2(pack2(q3.y), hp1[4 * dd + 1], a3);
                a0 = fma2(pack2(q0.z), hp1[4 * dd + 2], a0);
                a1 = fma2(pack2(q1.z), hp1[4 * dd + 2], a1);
                a2 = fma2(pack2(q2.z), hp1[4 * dd + 2], a2);
                a3 = fma2(pack2(q3.z), hp1[4 * dd + 2], a3);
                a0 = fma2(pack2(q0.w), hp1[4 * dd + 3], a0);
                a1 = fma2(pack2(q1.w), hp1[4 * dd + 3], a1);
                a2 = fma2(pack2(q2.w), hp1[4 * dd + 3], a2);
                a3 = fma2(pack2(q3.w), hp1[4 * dd + 3], a3);
            }
            const float4* v0 = reinterpret_cast<const float4*>(swf + F_W2HH + u * 8);
            const float4* v1 = reinterpret_cast<const float4*>(swf + F_W2HH + (8 + u) * 8);
            const float4* v2 = reinterpret_cast<const float4*>(swf + F_W2HH + (16 + u) * 8);
            const float4* v3 = reinterpret_cast<const float4*>(swf + F_W2HH + (24 + u) * 8);
#pragma unroll
            for (int jj = 0; jj < 2; ++jj) {
                float4 q0 = v0[jj], q1 = v1[jj], q2 = v2[jj], q3 = v3[jj];
                a0 = fma2(pack2(q0.x), hp2[4 * jj + 0], a0);
                a1 = fma2(pack2(q1.x), hp2[4 * jj + 0], a1);
                a2 = fma2(pack2(q2.x), hp2[4 * jj + 0], a2);
                a3 = fma2(pack2(q3.x), hp2[4 * jj + 0], a3);
                a0 = fma2(pack2(q0.y), hp2[4 * jj + 1], a0);
                a1 = fma2(pack2(q1.y), hp2[4 * jj + 1], a1);
                a2 = fma2(pack2(q2.y), hp2[4 * jj + 1], a2);
                a3 = fma2(pack2(q3.y), hp2[4 * jj + 1], a3);
                a0 = fma2(pack2(q0.z), hp2[4 * jj + 2], a0);
                a1 = fma2(pack2(q1.z), hp2[4 * jj + 2], a1);
                a2 = fma2(pack2(q2.z), hp2[4 * jj + 2], a2);
                a3 = fma2(pack2(q3.z), hp2[4 * jj + 2], a3);
                a0 = fma2(pack2(q0.w), hp2[4 * jj + 3], a0);
                a1 = fma2(pack2(q1.w), hp2[4 * jj + 3], a1);
                a2 = fma2(pack2(q2.w), hp2[4 * jj + 3], a2);
                a3 = fma2(pack2(q3.w), hp2[4 * jj + 3], a3);
            }
            float iA, iB, fA, fB, gA, gB, oA, oB;
            unpack2(a0, iA, iB);
            unpack2(a1, fA, fB);
            unpack2(a2, gA, gB);
            unpack2(a3, oA, oB);
            float cA0, cB0;
            unpack2(c2p[u], cA0, cB0);
            float cA = fmaf(sigf(fA), cA0, sigf(iA) * tanhx(gA));
            float cB = fmaf(sigf(fB), cB0, sigf(iB) * tanhx(gB));
            c2p[u] = pack2f(cA, cB);
            float hA = sigf(oA) * tanhx(cA);
            float hB = sigf(oB) * tanhx(cB);
            hn2p[u] = pack2f(hA, hB);
            hn2a[u] = hA;
            hn2b[u] = hB;
        }
#pragma unroll
        for (int j = 0; j < 8; ++j) hp2[j] = hn2p[j];

        // ---- e3 + decoder (scalar, tiny) for both elements ----
        lstm_small<1, 8>(sws + S_W3IH, sws + S_W3HH, sws + S_B3, hn2a, h3a, c3a);
        lstm_small<1, 8>(sws + S_W3IH, sws + S_W3HH, sws + S_B3, hn2b, h3b, c3b);

        float dva[1] = { h3a[0] };
        float dvb[1] = { h3b[0] };
        lstm_small<2, 1>(sws + S_D1IH, sws + S_D1HH, sws + S_BD1, dva, hd1a, cd1a);
        lstm_small<2, 1>(sws + S_D1IH, sws + S_D1HH, sws + S_BD1, dvb, hd1b, cd1b);
        lstm_small<2, 2>(sws + S_D2IH, sws + S_D2HH, sws + S_BD2, hd1a, hd2a, cd2a);
        lstm_small<2, 2>(sws + S_D2IH, sws + S_D2HH, sws + S_BD2, hd1b, hd2b, cd2b);
        lstm_small<1, 2>(sws + S_D3IH, sws + S_D3HH, sws + S_BD3, hd2a, hd3a, cd3a);
        lstm_small<1, 2>(sws + S_D3IH, sws + S_D3HH, sws + S_BD3, hd2b, hd3b, cd3b);

        u64 ypa = pack2(hd3a[0]);
        u64 ypb = pack2(hd3b[0]);
        const u64* gr = swp + P_G + t * 6;
#pragma unroll
        for (int j = 0; j < 6; ++j) {
            u64 g = gr[j];
            acc6a[j] = fma2(ypa, g, acc6a[j]);
            acc6b[j] = fma2(ypb, g, acc6b[j]);
        }
    }

    // ---- aux steps t = 48..59: decoder input = x[b, t-12, 4] ----
#pragma unroll 1
    for (int t = T; t < 60; ++t) {
        float dva[1] = { xb0[(t - 12) * 8 + 4] };
        float dvb[1] = { xb1[(t - 12) * 8 + 4] };
        lstm_small<2, 1>(sws + S_D1IH, sws + S_D1HH, sws + S_BD1, dva, hd1a, cd1a);
        lstm_small<2, 1>(sws + S_D1IH, sws + S_D1HH, sws + S_BD1, dvb, hd1b, cd1b);
        lstm_small<2, 2>(sws + S_D2IH, sws + S_D2HH, sws + S_BD2, hd1a, hd2a, cd2a);
        lstm_small<2, 2>(sws + S_D2IH, sws + S_D2HH, sws + S_BD2, hd1b, hd2b, cd2b);
        lstm_small<1, 2>(sws + S_D3IH, sws + S_D3HH, sws + S_BD3, hd2a, hd3a, cd3a);
        lstm_small<1, 2>(sws + S_D3IH, sws + S_D3HH, sws + S_BD3, hd2b, hd3b, cd3b);

        u64 ypa = pack2(hd3a[0]);
        u64 ypb = pack2(hd3b[0]);
        const u64* gr = swp + P_G + t * 6;
#pragma unroll
        for (int j = 0; j < 6; ++j) {
            u64 g = gr[j];
            acc6a[j] = fma2(ypa, g, acc6a[j]);
            acc6b[j] = fma2(ypb, g, acc6b[j]);
        }
    }

    // ---- epilogue ----
    float ra[12], rb[12];
#pragma unroll
    for (int j = 0; j < 6; ++j) {
        float lo, hi;
        unpack2(acc6a[j], lo, hi);
        ra[2 * j] = lo + sws[S_CB + 2 * j];
        ra[2 * j + 1] = hi + sws[S_CB + 2 * j + 1];
        unpack2(acc6b[j], lo, hi);
        rb[2 * j] = lo + sws[S_CB + 2 * j];
        rb[2 * j + 1] = hi + sws[S_CB + 2 * j + 1];
    }
    float4* op0 = reinterpret_cast<float4*>(out + (size_t)(2 * pair) * 12);
    op0[0] = make_float4(ra[0], ra[1], ra[2], ra[3]);
    op0[1] = make_float4(ra[4], ra[5], ra[6], ra[7]);
    op0[2] = make_float4(ra[8], ra[9], ra[10], ra[11]);
    float4* op1 = reinterpret_cast<float4*>(out + (size_t)(2 * pair + 1) * 12);
    op1[0] = make_float4(rb[0], rb[1], rb[2], rb[3]);
    op1[1] = make_float4(rb[4], rb[5], rb[6], rb[7]);
    op1[2] = make_float4(rb[8], rb[9], rb[10], rb[11]);
}

extern "C" void kernel_launch(void* const* d_in, const int* in_sizes, int n_in,
                              void* d_out, int out_size) {
    (void)in_sizes; (void)n_in; (void)out_size;
    const float* x    = (const float*)d_in[0];
    const float* w1ih = (const float*)d_in[1];
    const float* w1hh = (const float*)d_in[2];
    const float* b1   = (const float*)d_in[3];
    const float* w2ih = (const float*)d_in[4];
    const float* w2hh = (const float*)d_in[5];
    const float* b2   = (const float*)d_in[6];
    const float* w3ih = (const float*)d_in[7];
    const float* w3hh = (const float*)d_in[8];
    const float* b3   = (const float*)d_in[9];
    const float* d1ih = (const float*)d_in[10];
    const float* d1hh = (const float*)d_in[11];
    const float* bd1  = (const float*)d_in[12];
    const float* d2ih = (const float*)d_in[13];
    const float* d2hh = (const float*)d_in[14];
    const float* bd2  = (const float*)d_in[15];
    const float* d3ih = (const float*)d_in[16];
    const float* d3hh = (const float*)d_in[17];
    const float* bd3  = (const float*)d_in[18];
    const float* fc1w = (const float*)d_in[19];
    const float* fc1b = (const float*)d_in[20];
    const float* fc2w = (const float*)d_in[21];
    const float* fc2b = (const float*)d_in[22];
    float* out = (float*)d_out;

    dim3 grid(NTHREADS / TPB);
    dim3 block(TPB);
    vd_encdec_kernel<<<grid, block>>>(
        x, w1ih, w1hh, b1, w2ih, w2hh, b2, w3ih, w3hh, b3,
        d1ih, d1hh, bd1, d2ih, d2hh, bd2, d3ih, d3hh, bd3,
        fc1w, fc1b, fc2w, fc2b, out);
}